// round 3
// baseline (speedup 1.0000x reference)
#include <cuda_runtime.h>

#define NN 50000
#define EE 800000
#define GG 500
#define LL 3

// ---------------- scratch (static device globals; no allocation) ----------------
__device__ int   g_is64;
__device__ int   g_degi[NN];
__device__ float g_degf[NN];
__device__ float g_dinv[NN];
__device__ int   g_ptr[NN + 1];
__device__ int   g_cnt[NN];
__device__ int   g_csrc[EE];
__device__ float g_cw[EE];
__device__ float g_xc[NN * 128];   // [x | s] concat, row stride 128
__device__ float g_hin[NN * 128];  // xc + aggregated xc
__device__ float g_s[NN * 64];
__device__ float g_h1[NN * 64];
__device__ float g_hs[NN * 64];
__device__ float g_x2[NN * 64];
__device__ float g_pool[GG * 64];

// ---------------- index loading: int64 vs int32 auto-detect ----------------
__device__ __forceinline__ int ld_idx(const void* p, long i) {
    if (g_is64) return (int)((const long long*)p)[i];
    return ((const int*)p)[i];
}

__global__ void detect_k(const int* w) {
    if (blockIdx.x == 0 && threadIdx.x == 0) {
        int nz = 0;
#pragma unroll
        for (int j = 0; j < 8; j++)
            if (w[2 * j + 1] != 0) nz++;
        g_is64 = (nz == 0) ? 1 : 0;   // int64 little-endian => odd words are 0
    }
}

// ---------------- degree histogram ----------------
__global__ void hist_k(const void* ei) {
    int e = blockIdx.x * blockDim.x + threadIdx.x;
    if (e < EE) {
        int d = ld_idx(ei, (long)EE + e);
        atomicAdd(&g_degi[d], 1);
    }
}

__global__ void deg_k() {
    int i = blockIdx.x * blockDim.x + threadIdx.x;
    if (i < NN) {
        float d = (float)(g_degi[i] + 1);   // +1 self loop
        g_degf[i] = d;
        g_dinv[i] = rsqrtf(d);
    }
}

// ---------------- exclusive scan over degrees (single block) ----------------
__global__ void scan_k() {
    __shared__ int sh[1024];
    __shared__ int carry;
    int tid = threadIdx.x;
    if (tid == 0) carry = 0;
    __syncthreads();
    for (int base = 0; base < NN; base += 1024) {
        int i = base + tid;
        int v = (i < NN) ? g_degi[i] : 0;
        sh[tid] = v;
        __syncthreads();
        for (int off = 1; off < 1024; off <<= 1) {
            int t = (tid >= off) ? sh[tid - off] : 0;
            __syncthreads();
            sh[tid] += t;
            __syncthreads();
        }
        int incl = sh[tid];
        int c = carry;
        if (i < NN) g_ptr[i] = c + incl - v;
        __syncthreads();
        if (tid == 0) carry = c + sh[1023];
        __syncthreads();
    }
    if (tid == 0) g_ptr[NN] = carry;
}

// ---------------- CSR fill (src ids + gcn edge weights, grouped by dst) ----------------
__global__ void fill_k(const void* ei) {
    int e = blockIdx.x * blockDim.x + threadIdx.x;
    if (e < EE) {
        int sn = ld_idx(ei, e);
        int dn = ld_idx(ei, (long)EE + e);
        int pos = g_ptr[dn] + atomicAdd(&g_cnt[dn], 1);
        g_csrc[pos] = sn;
        g_cw[pos] = g_dinv[sn] * g_dinv[dn];
    }
}

// ---------------- GIN aggregation: warp per dst node, lane = one float4 of 128 ----------------
__global__ void gin_agg_k() {
    int nd = (blockIdx.x * blockDim.x + threadIdx.x) >> 5;
    if (nd >= NN) return;
    int lane = threadIdx.x & 31;
    const float4* xc4 = (const float4*)g_xc;
    int b = g_ptr[nd], e = g_ptr[nd + 1];
    float4 a0 = xc4[(long)nd * 32 + lane];   // self term (xc + agg)
    float4 a1 = make_float4(0.f, 0.f, 0.f, 0.f);
    int i = b;
    for (; i + 1 < e; i += 2) {
        int s0 = g_csrc[i], s1 = g_csrc[i + 1];
        float4 v0 = xc4[(long)s0 * 32 + lane];
        float4 v1 = xc4[(long)s1 * 32 + lane];
        a0.x += v0.x; a0.y += v0.y; a0.z += v0.z; a0.w += v0.w;
        a1.x += v1.x; a1.y += v1.y; a1.z += v1.z; a1.w += v1.w;
    }
    if (i < e) {
        int s0 = g_csrc[i];
        float4 v = xc4[(long)s0 * 32 + lane];
        a0.x += v.x; a0.y += v.y; a0.z += v.z; a0.w += v.w;
    }
    float4 r = make_float4(a0.x + a1.x, a0.y + a1.y, a0.z + a1.z, a0.w + a1.w);
    ((float4*)g_hin)[(long)nd * 32 + lane] = r;
}

// ---------------- GCN aggregation + tanh: warp per node, lane = float2 of 64 ----------------
__global__ void gcn_agg_k(const float* __restrict__ bias) {
    int nd = (blockIdx.x * blockDim.x + threadIdx.x) >> 5;
    if (nd >= NN) return;
    int lane = threadIdx.x & 31;
    const float2* hs2 = (const float2*)g_hs;
    int b = g_ptr[nd], e = g_ptr[nd + 1];
    float ax = 0.f, ay = 0.f, bx2 = 0.f, by2 = 0.f;
    int i = b;
    for (; i + 1 < e; i += 2) {
        float w0 = g_cw[i], w1 = g_cw[i + 1];
        int s0 = g_csrc[i], s1 = g_csrc[i + 1];
        float2 v0 = hs2[(long)s0 * 32 + lane];
        float2 v1 = hs2[(long)s1 * 32 + lane];
        ax = fmaf(w0, v0.x, ax); ay = fmaf(w0, v0.y, ay);
        bx2 = fmaf(w1, v1.x, bx2); by2 = fmaf(w1, v1.y, by2);
    }
    if (i < e) {
        float w0 = g_cw[i];
        int s0 = g_csrc[i];
        float2 v0 = hs2[(long)s0 * 32 + lane];
        ax = fmaf(w0, v0.x, ax); ay = fmaf(w0, v0.y, ay);
    }
    ax += bx2; ay += by2;
    float2 self = hs2[(long)nd * 32 + lane];
    float inv = 1.f / g_degf[nd];
    float rx = tanhf(ax + self.x * inv + bias[2 * lane]);
    float ry = tanhf(ay + self.y * inv + bias[2 * lane + 1]);
    ((float2*)g_s)[(long)nd * 32 + lane] = make_float2(rx, ry);
    ((float2*)g_xc)[(long)nd * 64 + 32 + lane] = make_float2(rx, ry);
}

// ---------------- GEMM: out[n x 64] = act(in[n x K] @ W[K x 64] + b) ----------------
// block = 64 rows x 64 cols, 256 threads, 4x4 register tile per thread.
template <int K, int ACT>
__global__ void gemm64_k(const float* __restrict__ in, const float* __restrict__ Wm,
                         const float* __restrict__ bias, int n,
                         float* __restrict__ outA, int ldA,
                         float* __restrict__ outB, int ldB) {
    constexpr int KC = (K < 64) ? K : 64;
    __shared__ float sIn[64][KC + 1];
    __shared__ float sW[KC][68];   // row stride 68 floats => 16B-aligned float4 reads

    int tid = threadIdx.x;
    int ct = tid & 15;    // col tile: cols 4*ct .. 4*ct+3
    int rt = tid >> 4;    // row tile: rows 4*rt .. 4*rt+3
    int rowBase = blockIdx.x * 64;

    float acc[4][4];
    float bseed[4];
#pragma unroll
    for (int c = 0; c < 4; c++) bseed[c] = bias ? bias[4 * ct + c] : 0.f;
#pragma unroll
    for (int r = 0; r < 4; r++)
#pragma unroll
        for (int c = 0; c < 4; c++) acc[r][c] = bseed[c];

    for (int kb = 0; kb < K; kb += KC) {
        for (int idx = tid; idx < 64 * KC; idx += 256) {
            int r = idx / KC, k = idx % KC;
            int gr = rowBase + r;
            sIn[r][k] = (gr < n) ? in[(long)gr * K + kb + k] : 0.f;
        }
        for (int idx = tid; idx < KC * 64; idx += 256) {
            int k = idx / 64, c = idx % 64;
            sW[k][c] = Wm[(long)(kb + k) * 64 + c];
        }
        __syncthreads();
#pragma unroll
        for (int k = 0; k < KC; k++) {
            float a0 = sIn[4 * rt + 0][k];
            float a1 = sIn[4 * rt + 1][k];
            float a2 = sIn[4 * rt + 2][k];
            float a3 = sIn[4 * rt + 3][k];
            float4 w = *(const float4*)&sW[k][4 * ct];
            acc[0][0] = fmaf(a0, w.x, acc[0][0]); acc[0][1] = fmaf(a0, w.y, acc[0][1]);
            acc[0][2] = fmaf(a0, w.z, acc[0][2]); acc[0][3] = fmaf(a0, w.w, acc[0][3]);
            acc[1][0] = fmaf(a1, w.x, acc[1][0]); acc[1][1] = fmaf(a1, w.y, acc[1][1]);
            acc[1][2] = fmaf(a1, w.z, acc[1][2]); acc[1][3] = fmaf(a1, w.w, acc[1][3]);
            acc[2][0] = fmaf(a2, w.x, acc[2][0]); acc[2][1] = fmaf(a2, w.y, acc[2][1]);
            acc[2][2] = fmaf(a2, w.z, acc[2][2]); acc[2][3] = fmaf(a2, w.w, acc[2][3]);
            acc[3][0] = fmaf(a3, w.x, acc[3][0]); acc[3][1] = fmaf(a3, w.y, acc[3][1]);
            acc[3][2] = fmaf(a3, w.z, acc[3][2]); acc[3][3] = fmaf(a3, w.w, acc[3][3]);
        }
        __syncthreads();
    }

#pragma unroll
    for (int r = 0; r < 4; r++) {
        int gr = rowBase + 4 * rt + r;
        if (gr < n) {
#pragma unroll
            for (int c = 0; c < 4; c++) {
                float v = acc[r][c];
                if (ACT) v = fmaxf(v, 0.f);
                outA[(long)gr * ldA + 4 * ct + c] = v;
                if (outB) outB[(long)gr * ldB + 4 * ct + c] = v;
            }
        }
    }
}

// ---------------- global add pool ----------------
__global__ void pool_k(const void* batch) {
    int idx = blockIdx.x * blockDim.x + threadIdx.x;
    if (idx >= NN * 64) return;
    int nno = idx >> 6;
    int c = idx & 63;
    int b = ld_idx(batch, nno);
    atomicAdd(&g_pool[b * 64 + c], g_x2[idx]);
}

// ---------------- head: post linear + relu + readout + log_softmax ----------------
__global__ void head_k(const float* __restrict__ postW, const float* __restrict__ postb,
                       const float* __restrict__ roW, const float* __restrict__ rob,
                       float* __restrict__ out) {
    int row = blockIdx.x;
    int t = threadIdx.x;   // 64 threads
    __shared__ float sg[64], sh1[64], sl[10];
    sg[t] = g_pool[row * 64 + t];
    __syncthreads();
    float acc = postb[t];
#pragma unroll
    for (int k = 0; k < 64; k++) acc = fmaf(sg[k], postW[k * 64 + t], acc);
    sh1[t] = fmaxf(acc, 0.f);
    __syncthreads();
    if (t < 10) {
        float a = rob[t];
#pragma unroll
        for (int k = 0; k < 64; k++) a = fmaf(sh1[k], roW[k * 10 + t], a);
        sl[t] = a;
    }
    __syncthreads();
    if (t == 0) {
        float m = sl[0];
#pragma unroll
        for (int c = 1; c < 10; c++) m = fmaxf(m, sl[c]);
        float sum = 0.f;
#pragma unroll
        for (int c = 0; c < 10; c++) sum += expf(sl[c] - m);
        float lse = m + logf(sum);
#pragma unroll
        for (int c = 0; c < 10; c++) out[row * 10 + c] = sl[c] - lse;
    }
}

// ---------------- launch ----------------
extern "C" void kernel_launch(void* const* d_in, const int* in_sizes, int n_in,
                              void* d_out, int out_size) {
    const float* x_in  = (const float*)d_in[0];
    const float* s_in  = (const float*)d_in[1];
    const void*  ei    = d_in[2];
    const void*  batch = d_in[3];
    const float* preW  = (const float*)d_in[4];
    const float* preb  = (const float*)d_in[5];
    const float* embW  = (const float*)d_in[6];
    const float* embb  = (const float*)d_in[7];
    const float* ginW1 = (const float*)d_in[8];
    const float* ginb1 = (const float*)d_in[9];
    const float* ginW2 = (const float*)d_in[10];
    const float* ginb2 = (const float*)d_in[11];
    const float* gcnW  = (const float*)d_in[12];
    const float* gcnb  = (const float*)d_in[13];
    const float* whpW  = (const float*)d_in[14];
    const float* whpb  = (const float*)d_in[15];
    const float* postW = (const float*)d_in[16];
    const float* postb = (const float*)d_in[17];
    const float* roW   = (const float*)d_in[18];
    const float* rob   = (const float*)d_in[19];
    float* out = (float*)d_out;

    void *p_degi, *p_cnt, *p_pool, *p_xc, *p_hin, *p_s, *p_h1, *p_hs, *p_x2;
    cudaGetSymbolAddress(&p_degi, g_degi);
    cudaGetSymbolAddress(&p_cnt, g_cnt);
    cudaGetSymbolAddress(&p_pool, g_pool);
    cudaGetSymbolAddress(&p_xc, g_xc);
    cudaGetSymbolAddress(&p_hin, g_hin);
    cudaGetSymbolAddress(&p_s, g_s);
    cudaGetSymbolAddress(&p_h1, g_h1);
    cudaGetSymbolAddress(&p_hs, g_hs);
    cudaGetSymbolAddress(&p_x2, g_x2);
    float* xc = (float*)p_xc;
    float* hin = (float*)p_hin;
    float* sbuf = (float*)p_s;
    float* h1 = (float*)p_h1;
    float* hs = (float*)p_hs;
    float* x2 = (float*)p_x2;

    // zero transient counters / pool
    cudaMemsetAsync(p_degi, 0, NN * sizeof(int), 0);
    cudaMemsetAsync(p_cnt, 0, NN * sizeof(int), 0);
    cudaMemsetAsync(p_pool, 0, GG * 64 * sizeof(float), 0);

    detect_k<<<1, 32>>>((const int*)ei);

    const int TB = 256;
    const int gridE = (EE + TB - 1) / TB;
    const int gridN = (NN + TB - 1) / TB;
    const int gridW = (NN * 32 + TB - 1) / TB;          // warp-per-node kernels
    const int gridM = (NN + 63) / 64;                   // gemm blocks

    hist_k<<<gridE, TB>>>(ei);
    deg_k<<<gridN, TB>>>();
    scan_k<<<1, 1024>>>();
    fill_k<<<gridE, TB>>>(ei);

    // pre: x -> xc[:, :64];  emb: s -> s buf and xc[:, 64:]
    gemm64_k<128, 0><<<gridM, TB>>>(x_in, preW, preb, NN, xc, 128, nullptr, 0);
    gemm64_k<16, 0><<<gridM, TB>>>(s_in, embW, embb, NN, sbuf, 64, xc + 64, 128);

    for (int i = 0; i < LL; i++) {
        gin_agg_k<<<gridW, TB>>>();
        gemm64_k<128, 1><<<gridM, TB>>>(hin, ginW1 + (long)i * 128 * 64, ginb1 + i * 64,
                                        NN, h1, 64, nullptr, 0);
        gemm64_k<64, 1><<<gridM, TB>>>(h1, ginW2 + (long)i * 64 * 64, ginb2 + i * 64,
                                       NN, xc, 128, nullptr, 0);
        gemm64_k<64, 0><<<gridM, TB>>>(sbuf, gcnW + (long)i * 64 * 64, nullptr,
                                       NN, hs, 64, nullptr, 0);
        gcn_agg_k<<<gridW, TB>>>(gcnb + i * 64);
    }

    gemm64_k<128, 0><<<gridM, TB>>>(xc, whpW, whpb, NN, x2, 64, nullptr, 0);
    pool_k<<<(NN * 64 + TB - 1) / TB, TB>>>(batch);
    head_k<<<GG, 64>>>(postW, postb, roW, rob, out);
}

// round 4
// speedup vs baseline: 1.9265x; 1.9265x over previous
#include <cuda_runtime.h>

#define NN 50000
#define EE 800000
#define GG 500
#define LL 3
#define NB1 ((NN + 1023) / 1024)

// ---------------- scratch (static device globals; no allocation) ----------------
__device__ int   g_is64;
__device__ int   g_degi[NN];
__device__ float g_degf[NN];
__device__ float g_dinv[NN];
__device__ int   g_ptr[NN + 1];
__device__ int   g_cnt[NN];
__device__ int   g_bsum[64];
__device__ int   g_boff[65];
__device__ int   g_csrc[EE];
__device__ float g_cw[EE];
__device__ float g_xc[NN * 128];   // [x | s] concat, row stride 128
__device__ float g_hin[NN * 128];  // xc + aggregated xc
__device__ float g_s[NN * 64];
__device__ float g_h1[NN * 64];
__device__ float g_hs[NN * 64];
__device__ float g_x2[NN * 64];

// ---------------- index loading: int64 vs int32 auto-detect ----------------
__device__ __forceinline__ int ld_idx(const void* p, long i) {
    if (g_is64) return (int)((const long long*)p)[i];
    return ((const int*)p)[i];
}

__global__ void detect_k(const int* w) {
    if (blockIdx.x == 0 && threadIdx.x == 0) {
        int nz = 0;
#pragma unroll
        for (int j = 0; j < 8; j++)
            if (w[2 * j + 1] != 0) nz++;
        g_is64 = (nz == 0) ? 1 : 0;   // int64 little-endian => odd words are 0
    }
}

// ---------------- degree histogram ----------------
__global__ void hist_k(const void* ei) {
    int e = blockIdx.x * blockDim.x + threadIdx.x;
    if (e < EE) {
        int d = ld_idx(ei, (long)EE + e);
        atomicAdd(&g_degi[d], 1);
    }
}

__global__ void deg_k() {
    int i = blockIdx.x * blockDim.x + threadIdx.x;
    if (i < NN) {
        float d = (float)(g_degi[i] + 1);   // +1 self loop
        g_degf[i] = d;
        g_dinv[i] = rsqrtf(d);
    }
}

// ---------------- multi-block exclusive scan over degrees ----------------
// phase 1: per-block inclusive scan of 1024 elems; write (incl - v) and block sum
__global__ void scan1_k() {
    __shared__ int sh[1024];
    int tid = threadIdx.x;
    int i = blockIdx.x * 1024 + tid;
    int v = (i < NN) ? g_degi[i] : 0;
    sh[tid] = v;
    __syncthreads();
    for (int off = 1; off < 1024; off <<= 1) {
        int t = (tid >= off) ? sh[tid - off] : 0;
        __syncthreads();
        sh[tid] += t;
        __syncthreads();
    }
    int incl = sh[tid];
    if (i < NN) g_ptr[i] = incl - v;
    if (tid == 1023) g_bsum[blockIdx.x] = incl;
}

// phase 2: serial exclusive scan of NB1 block sums (tiny)
__global__ void scan2_k() {
    if (threadIdx.x == 0) {
        int c = 0;
        for (int b = 0; b < NB1; b++) { g_boff[b] = c; c += g_bsum[b]; }
        g_boff[NB1] = c;
    }
}

// phase 3: add block offsets; write total
__global__ void scan3_k() {
    int i = blockIdx.x * blockDim.x + threadIdx.x;
    if (i < NN) g_ptr[i] += g_boff[i >> 10];
    if (i == 0) g_ptr[NN] = g_boff[NB1];
}

// ---------------- CSR fill (src ids + gcn edge weights, grouped by dst) ----------------
__global__ void fill_k(const void* ei) {
    int e = blockIdx.x * blockDim.x + threadIdx.x;
    if (e < EE) {
        int sn = ld_idx(ei, e);
        int dn = ld_idx(ei, (long)EE + e);
        int pos = g_ptr[dn] + atomicAdd(&g_cnt[dn], 1);
        g_csrc[pos] = sn;
        g_cw[pos] = g_dinv[sn] * g_dinv[dn];
    }
}

// ---------------- GIN aggregation: warp per dst node, lane = one float4 of 128 ----------------
__global__ void gin_agg_k() {
    int nd = (blockIdx.x * blockDim.x + threadIdx.x) >> 5;
    if (nd >= NN) return;
    int lane = threadIdx.x & 31;
    const float4* xc4 = (const float4*)g_xc;
    int b = g_ptr[nd], e = g_ptr[nd + 1];
    float4 a0 = xc4[(long)nd * 32 + lane];   // self term (xc + agg)
    float4 a1 = make_float4(0.f, 0.f, 0.f, 0.f);
    int i = b;
    for (; i + 1 < e; i += 2) {
        int s0 = g_csrc[i], s1 = g_csrc[i + 1];
        float4 v0 = xc4[(long)s0 * 32 + lane];
        float4 v1 = xc4[(long)s1 * 32 + lane];
        a0.x += v0.x; a0.y += v0.y; a0.z += v0.z; a0.w += v0.w;
        a1.x += v1.x; a1.y += v1.y; a1.z += v1.z; a1.w += v1.w;
    }
    if (i < e) {
        int s0 = g_csrc[i];
        float4 v = xc4[(long)s0 * 32 + lane];
        a0.x += v.x; a0.y += v.y; a0.z += v.z; a0.w += v.w;
    }
    float4 r = make_float4(a0.x + a1.x, a0.y + a1.y, a0.z + a1.z, a0.w + a1.w);
    ((float4*)g_hin)[(long)nd * 32 + lane] = r;
}

// ---------------- GCN aggregation + tanh: warp per node, lane = float2 of 64 ----------------
__global__ void gcn_agg_k(const float* __restrict__ bias) {
    int nd = (blockIdx.x * blockDim.x + threadIdx.x) >> 5;
    if (nd >= NN) return;
    int lane = threadIdx.x & 31;
    const float2* hs2 = (const float2*)g_hs;
    int b = g_ptr[nd], e = g_ptr[nd + 1];
    float ax = 0.f, ay = 0.f, bx2 = 0.f, by2 = 0.f;
    int i = b;
    for (; i + 1 < e; i += 2) {
        float w0 = g_cw[i], w1 = g_cw[i + 1];
        int s0 = g_csrc[i], s1 = g_csrc[i + 1];
        float2 v0 = hs2[(long)s0 * 32 + lane];
        float2 v1 = hs2[(long)s1 * 32 + lane];
        ax = fmaf(w0, v0.x, ax); ay = fmaf(w0, v0.y, ay);
        bx2 = fmaf(w1, v1.x, bx2); by2 = fmaf(w1, v1.y, by2);
    }
    if (i < e) {
        float w0 = g_cw[i];
        int s0 = g_csrc[i];
        float2 v0 = hs2[(long)s0 * 32 + lane];
        ax = fmaf(w0, v0.x, ax); ay = fmaf(w0, v0.y, ay);
    }
    ax += bx2; ay += by2;
    float2 self = hs2[(long)nd * 32 + lane];
    float inv = 1.f / g_degf[nd];
    float rx = tanhf(ax + self.x * inv + bias[2 * lane]);
    float ry = tanhf(ay + self.y * inv + bias[2 * lane + 1]);
    ((float2*)g_s)[(long)nd * 32 + lane] = make_float2(rx, ry);
    ((float2*)g_xc)[(long)nd * 64 + 32 + lane] = make_float2(rx, ry);
}

// ---------------- GEMM: out[n x 64] = act(in[n x K] @ W[K x 64] + b) ----------------
// block = 128 rows x 64 cols, 256 threads, 8x4 register tile, KC<=32 k-chunks.
// 25.6KB smem/block -> high occupancy; 391-block grid = single wave on 148 SMs.
template <int K, int ACT>
__global__ void gemm64_k(const float* __restrict__ in, const float* __restrict__ Wm,
                         const float* __restrict__ bias, int n,
                         float* __restrict__ outA, int ldA,
                         float* __restrict__ outB, int ldB) {
    constexpr int KC = (K < 32) ? K : 32;
    __shared__ float sIn[128][KC + 1];
    __shared__ float sW[KC][68];   // row stride 68 floats => 16B-aligned float4 reads

    int tid = threadIdx.x;
    int ct = tid & 15;    // col tile: cols 4*ct .. 4*ct+3
    int rt = tid >> 4;    // row tile: rows 8*rt .. 8*rt+7
    int rowBase = blockIdx.x * 128;

    float acc[8][4];
    float bseed[4];
#pragma unroll
    for (int c = 0; c < 4; c++) bseed[c] = bias ? bias[4 * ct + c] : 0.f;
#pragma unroll
    for (int r = 0; r < 8; r++)
#pragma unroll
        for (int c = 0; c < 4; c++) acc[r][c] = bseed[c];

    for (int kb = 0; kb < K; kb += KC) {
        for (int idx = tid; idx < 128 * KC; idx += 256) {
            int r = idx / KC, k = idx - r * KC;
            int gr = rowBase + r;
            sIn[r][k] = (gr < n) ? in[(long)gr * K + kb + k] : 0.f;
        }
        for (int idx = tid; idx < KC * 64; idx += 256) {
            int k = idx >> 6, c = idx & 63;
            sW[k][c] = Wm[(long)(kb + k) * 64 + c];
        }
        __syncthreads();
#pragma unroll 8
        for (int k = 0; k < KC; k++) {
            float4 w = *(const float4*)&sW[k][4 * ct];
            float a[8];
#pragma unroll
            for (int j = 0; j < 8; j++) a[j] = sIn[8 * rt + j][k];
#pragma unroll
            for (int j = 0; j < 8; j++) {
                acc[j][0] = fmaf(a[j], w.x, acc[j][0]);
                acc[j][1] = fmaf(a[j], w.y, acc[j][1]);
                acc[j][2] = fmaf(a[j], w.z, acc[j][2]);
                acc[j][3] = fmaf(a[j], w.w, acc[j][3]);
            }
        }
        __syncthreads();
    }

#pragma unroll
    for (int r = 0; r < 8; r++) {
        int gr = rowBase + 8 * rt + r;
        if (gr < n) {
#pragma unroll
            for (int c = 0; c < 4; c++) {
                float v = acc[r][c];
                if (ACT) v = fmaxf(v, 0.f);
                outA[(long)gr * ldA + 4 * ct + c] = v;
                if (outB) outB[(long)gr * ldB + 4 * ct + c] = v;
            }
        }
    }
}

// ---------------- fused global add pool + post + readout + log_softmax ----------------
// batch is sorted -> binary-search each graph's node range; no atomics, no pool buf.
__global__ void poolhead_k(const void* __restrict__ batch,
                           const float* __restrict__ postW, const float* __restrict__ postb,
                           const float* __restrict__ roW, const float* __restrict__ rob,
                           float* __restrict__ out) {
    int g = blockIdx.x;
    int t = threadIdx.x;   // 64 threads, one output column each
    // lower_bound(batch, g)
    int lo = 0, hi = NN;
    while (lo < hi) { int mid = (lo + hi) >> 1; if (ld_idx(batch, mid) < g) lo = mid + 1; else hi = mid; }
    int beg = lo;
    hi = NN;
    while (lo < hi) { int mid = (lo + hi) >> 1; if (ld_idx(batch, mid) < g + 1) lo = mid + 1; else hi = mid; }
    int end = lo;

    float acc = 0.f;
    for (int nd = beg; nd < end; nd++) acc += g_x2[(long)nd * 64 + t];

    __shared__ float sg[64], sh1[64], sl[10];
    sg[t] = acc;
    __syncthreads();
    float a = postb[t];
#pragma unroll
    for (int k = 0; k < 64; k++) a = fmaf(sg[k], postW[k * 64 + t], a);
    sh1[t] = fmaxf(a, 0.f);
    __syncthreads();
    if (t < 10) {
        float r = rob[t];
#pragma unroll
        for (int k = 0; k < 64; k++) r = fmaf(sh1[k], roW[k * 10 + t], r);
        sl[t] = r;
    }
    __syncthreads();
    if (t == 0) {
        float m = sl[0];
#pragma unroll
        for (int c = 1; c < 10; c++) m = fmaxf(m, sl[c]);
        float sum = 0.f;
#pragma unroll
        for (int c = 0; c < 10; c++) sum += expf(sl[c] - m);
        float lse = m + logf(sum);
#pragma unroll
        for (int c = 0; c < 10; c++) out[g * 10 + c] = sl[c] - lse;
    }
}

// ---------------- launch ----------------
extern "C" void kernel_launch(void* const* d_in, const int* in_sizes, int n_in,
                              void* d_out, int out_size) {
    const float* x_in  = (const float*)d_in[0];
    const float* s_in  = (const float*)d_in[1];
    const void*  ei    = d_in[2];
    const void*  batch = d_in[3];
    const float* preW  = (const float*)d_in[4];
    const float* preb  = (const float*)d_in[5];
    const float* embW  = (const float*)d_in[6];
    const float* embb  = (const float*)d_in[7];
    const float* ginW1 = (const float*)d_in[8];
    const float* ginb1 = (const float*)d_in[9];
    const float* ginW2 = (const float*)d_in[10];
    const float* ginb2 = (const float*)d_in[11];
    const float* gcnW  = (const float*)d_in[12];
    const float* gcnb  = (const float*)d_in[13];
    const float* whpW  = (const float*)d_in[14];
    const float* whpb  = (const float*)d_in[15];
    const float* postW = (const float*)d_in[16];
    const float* postb = (const float*)d_in[17];
    const float* roW   = (const float*)d_in[18];
    const float* rob   = (const float*)d_in[19];
    float* out = (float*)d_out;

    void *p_degi, *p_cnt, *p_xc, *p_hin, *p_s, *p_h1, *p_hs, *p_x2;
    cudaGetSymbolAddress(&p_degi, g_degi);
    cudaGetSymbolAddress(&p_cnt, g_cnt);
    cudaGetSymbolAddress(&p_xc, g_xc);
    cudaGetSymbolAddress(&p_hin, g_hin);
    cudaGetSymbolAddress(&p_s, g_s);
    cudaGetSymbolAddress(&p_h1, g_h1);
    cudaGetSymbolAddress(&p_hs, g_hs);
    cudaGetSymbolAddress(&p_x2, g_x2);
    float* xc = (float*)p_xc;
    float* hin = (float*)p_hin;
    float* sbuf = (float*)p_s;
    float* h1 = (float*)p_h1;
    float* hs = (float*)p_hs;
    float* x2 = (float*)p_x2;

    // zero transient counters
    cudaMemsetAsync(p_degi, 0, NN * sizeof(int), 0);
    cudaMemsetAsync(p_cnt, 0, NN * sizeof(int), 0);

    detect_k<<<1, 32>>>((const int*)ei);

    const int TB = 256;
    const int gridE = (EE + TB - 1) / TB;
    const int gridN = (NN + TB - 1) / TB;
    const int gridW = (NN * 32 + TB - 1) / TB;          // warp-per-node kernels
    const int gridM = (NN + 127) / 128;                 // gemm blocks (128-row tiles)

    hist_k<<<gridE, TB>>>(ei);
    deg_k<<<gridN, TB>>>();
    scan1_k<<<NB1, 1024>>>();
    scan2_k<<<1, 32>>>();
    scan3_k<<<gridN, TB>>>();
    fill_k<<<gridE, TB>>>(ei);

    // pre: x -> xc[:, :64];  emb: s -> s buf and xc[:, 64:]
    gemm64_k<128, 0><<<gridM, TB>>>(x_in, preW, preb, NN, xc, 128, nullptr, 0);
    gemm64_k<16, 0><<<gridM, TB>>>(s_in, embW, embb, NN, sbuf, 64, xc + 64, 128);

    for (int i = 0; i < LL; i++) {
        gin_agg_k<<<gridW, TB>>>();
        gemm64_k<128, 1><<<gridM, TB>>>(hin, ginW1 + (long)i * 128 * 64, ginb1 + i * 64,
                                        NN, h1, 64, nullptr, 0);
        gemm64_k<64, 1><<<gridM, TB>>>(h1, ginW2 + (long)i * 64 * 64, ginb2 + i * 64,
                                       NN, xc, 128, nullptr, 0);
        gemm64_k<64, 0><<<gridM, TB>>>(sbuf, gcnW + (long)i * 64 * 64, nullptr,
                                       NN, hs, 64, nullptr, 0);
        gcn_agg_k<<<gridW, TB>>>(gcnb + i * 64);
    }

    gemm64_k<128, 0><<<gridM, TB>>>(xc, whpW, whpb, NN, x2, 64, nullptr, 0);
    poolhead_k<<<GG, 64>>>(batch, postW, postb, roW, rob, out);
}